// round 11
// baseline (speedup 1.0000x reference)
#include <cuda_runtime.h>
#include <math.h>

#define B_ 8
#define L_ 512
#define S_ 128
#define D_ 256
#define M_ (B_*L_)
#define EPSV 1e-12f
#define TARGETW (1.0f/2000.0f)

// ---------------- scratch (static device memory; no allocation) ----------------
__device__ float g_Q[M_*D_];
__device__ float g_K[M_*D_];
__device__ float g_V[M_*D_];
__device__ float g_gate[M_];
__device__ float g_invQ[M_];
__device__ float g_invK[M_];

// ---------------- helpers ----------------
// NOTE: redux.sync.add.f32 is NOT supported by ptxas for sm_103 (verified R4).
// Keep the shfl butterfly.
__device__ __forceinline__ float wredsum(float v){
    v += __shfl_xor_sync(0xffffffffu, v, 16);
    v += __shfl_xor_sync(0xffffffffu, v, 8);
    v += __shfl_xor_sync(0xffffffffu, v, 4);
    v += __shfl_xor_sync(0xffffffffu, v, 2);
    v += __shfl_xor_sync(0xffffffffu, v, 1);
    return v;
}
__device__ __forceinline__ float dot4f(float4 a, float4 b, float acc){
    acc = fmaf(a.x, b.x, acc); acc = fmaf(a.y, b.y, acc);
    acc = fmaf(a.z, b.z, acc); acc = fmaf(a.w, b.w, acc);
    return acc;
}

// ---------------- QKV projection GEMM: C[m][n] = sum_k A[m][k]*W[n][k] + bias[n] ----------------
__global__ void gemm_nt(const float* __restrict__ A, const float* __restrict__ W,
                        const float* __restrict__ bias, float* __restrict__ C)
{
    constexpr int TM = 64, TN = 64, TK = 16, K = D_, N = D_;
    __shared__ __align__(16) float As[TK][TM];
    __shared__ __align__(16) float Bs[TK][TN];
    int bm = blockIdx.x * TM, bn = blockIdx.y * TN;
    int tid = threadIdx.x;
    int lrow = tid >> 2, lk = (tid & 3) * 4;
    int ty = (tid >> 4) << 2, tx = (tid & 15) << 2;
    float acc[4][4];
    #pragma unroll
    for (int i = 0; i < 4; i++)
        #pragma unroll
        for (int j = 0; j < 4; j++) acc[i][j] = 0.f;

    for (int k0 = 0; k0 < K; k0 += TK){
        float4 av = *(const float4*)(A + (size_t)(bm + lrow)*K + k0 + lk);
        float4 bv = *(const float4*)(W + (size_t)(bn + lrow)*K + k0 + lk);
        __syncthreads();
        As[lk+0][lrow]=av.x; As[lk+1][lrow]=av.y; As[lk+2][lrow]=av.z; As[lk+3][lrow]=av.w;
        Bs[lk+0][lrow]=bv.x; Bs[lk+1][lrow]=bv.y; Bs[lk+2][lrow]=bv.z; Bs[lk+3][lrow]=bv.w;
        __syncthreads();
        #pragma unroll
        for (int kk = 0; kk < TK; kk++){
            float4 a = *(const float4*)&As[kk][ty];
            float4 b = *(const float4*)&Bs[kk][tx];
            float ar[4] = {a.x, a.y, a.z, a.w};
            float br[4] = {b.x, b.y, b.z, b.w};
            #pragma unroll
            for (int i = 0; i < 4; i++)
                #pragma unroll
                for (int j = 0; j < 4; j++)
                    acc[i][j] = fmaf(ar[i], br[j], acc[i][j]);
        }
    }
    float4 b4 = *(const float4*)(bias + bn + tx);
    float bb[4] = {b4.x, b4.y, b4.z, b4.w};
    #pragma unroll
    for (int i = 0; i < 4; i++){
        float4 o;
        o.x = acc[i][0] + bb[0]; o.y = acc[i][1] + bb[1];
        o.z = acc[i][2] + bb[2]; o.w = acc[i][3] + bb[3];
        *(float4*)(C + (size_t)(bm + ty + i)*N + bn + tx) = o;
    }
}

// ---------------- gate: sigmoid(h . Wg + bg), one warp per row ----------------
__global__ void gate_kernel(const float* __restrict__ H, const float* __restrict__ Wg,
                            const float* __restrict__ bg)
{
    int gw = (blockIdx.x * blockDim.x + threadIdx.x) >> 5;
    int l = threadIdx.x & 31;
    if (gw >= M_) return;
    const float* h = H + (size_t)gw * D_;
    float s = 0.f;
    #pragma unroll 4
    for (int k = l; k < D_; k += 32) s = fmaf(h[k], Wg[k], s);
    s = wredsum(s);
    if (l == 0) g_gate[gw] = 1.f / (1.f + __expf(-(s + bg[0])));
}

// ---------------- 1/max(||q||,eps), 1/max(||k||,eps): one warp per row ----------------
__global__ void invnorm_kernel()
{
    int gw = (blockIdx.x * blockDim.x + threadIdx.x) >> 5;
    int l = threadIdx.x & 31;
    if (gw >= M_) return;
    const float* q = g_Q + (size_t)gw * D_;
    const float* k = g_K + (size_t)gw * D_;
    float sq = 0.f, sk = 0.f;
    #pragma unroll 4
    for (int i = l; i < D_; i += 32){
        float qv = q[i], kv = k[i];
        sq = fmaf(qv, qv, sq);
        sk = fmaf(kv, kv, sk);
    }
    sq = wredsum(sq); sk = wredsum(sk);
    if (l == 0){
        g_invQ[gw] = 1.f / fmaxf(sqrtf(sq), EPSV);
        g_invK[gw] = 1.f / fmaxf(sqrtf(sk), EPSV);
    }
}

// ---------------- sp scalar: mean_t (mean_b gate - target)^2 ----------------
__global__ void sp_kernel(float* __restrict__ out, int out_size)
{
    __shared__ float red[512];
    int t = threadIdx.x;   // L_ = 512 exactly
    float g = 0.f;
    #pragma unroll
    for (int b = 0; b < B_; b++) g += g_gate[b * L_ + t];
    g *= (1.f / (float)B_);
    float d = g - TARGETW;
    red[t] = d * d;
    __syncthreads();
    for (int off = 256; off > 0; off >>= 1){
        if (t < off) red[t] += red[t + off];
        __syncthreads();
    }
    if (t == 0 && out_size > M_ * D_) out[M_ * D_] = red[0] * (1.f / (float)L_);
}

// ---------------- persistent recurrence: one CTA per batch, mem in smem ----------------
__global__ void __launch_bounds__(512, 1) recur_kernel(
    const float* __restrict__ Minit, const float* __restrict__ masks,
    float* __restrict__ out)
{
    constexpr int NW = 16;           // warps
    constexpr int RPW = S_ / NW;     // rows per warp = 8
    extern __shared__ __align__(16) float sm[];
    float* mem   = sm;                       // S_*D_
    float* dotq  = sm + S_*D_;               // S_
    float* dotk  = dotq + S_;
    float* nrm   = dotk + S_;
    float* rw    = nrm + S_;
    float* pc    = rw + S_;
    float* rc    = pc + S_;
    float* readp = rc + S_;                  // NW*D_
    float* sred  = readp + NW*D_;            // 8

    int b = blockIdx.x;
    int tid = threadIdx.x, w = tid >> 5, l = tid & 31;
    float4* mem4 = (float4*)mem;

    // load initial memory
    const float4* M4 = (const float4*)(Minit + (size_t)b * S_ * D_);
    for (int i = tid; i < S_ * D_ / 4; i += 512) mem4[i] = M4[i];
    __syncthreads();

    // prologue: dots/norms of initial mem against raw q0, k0
    {
        const float4* Qp = (const float4*)(g_Q + (size_t)(b * L_) * D_);
        const float4* Kp = (const float4*)(g_K + (size_t)(b * L_) * D_);
        float4 q0 = Qp[l], q1 = Qp[32 + l], k0 = Kp[l], k1 = Kp[32 + l];
        #pragma unroll
        for (int i = 0; i < RPW; i++){
            int s = w * RPW + i;
            float4 m0 = mem4[s*64 + l], m1 = mem4[s*64 + 32 + l];
            float dq = dot4f(m0, q0, dot4f(m1, q1, 0.f));
            float dk = dot4f(m0, k0, dot4f(m1, k1, 0.f));
            float nn = dot4f(m0, m0, dot4f(m1, m1, 0.f));
            dq = wredsum(dq); dk = wredsum(dk); nn = wredsum(nn);
            if (l == 0){ dotq[s] = dq; dotk[s] = dk; nrm[s] = nn; }
        }
    }
    __syncthreads();

    for (int t = 0; t < L_; t++){
        float eq = 0.f, ew = 0.f;
        // phase A: warps 0-3 softmax exponentials; warps 4-11 finish read_v of step t-1
        if (tid < S_){
            int s = tid;
            float inv = 1.f / fmaxf(sqrtf(nrm[s]), EPSV);
            float iq = g_invQ[b*L_ + t] * inv;
            float ik = g_invK[b*L_ + t] * inv;
            eq = __expf(2.f * dotq[s] * iq);
            ew = __expf(2.f * dotk[s] * ik);
            float sq = wredsum(eq), sw = wredsum(ew);
            if (l == 0){ sred[w*2] = sq; sred[w*2 + 1] = sw; }
        } else if (tid < S_ + D_ && t > 0){
            int d = tid - S_;
            float acc = 0.f;
            #pragma unroll
            for (int j = 0; j < NW; j++) acc += readp[j*D_ + d];
            out[(size_t)(b*L_ + (t-1))*D_ + d] = acc;
        }
        __syncthreads();
        // phase B: finalize softmax -> rw, and update coefficients pc/rc (mask folded in)
        if (tid < S_){
            int s = tid;
            float SQ = sred[0] + sred[2] + sred[4] + sred[6];
            float SW = sred[1] + sred[3] + sred[5] + sred[7];
            float g = g_gate[b*L_ + t];
            float mval = masks[b*L_ + t];
            rw[s] = eq / SQ;
            float c = g * (ew / SW);
            pc[s] = mval * (1.f - c);
            rc[s] = mval * c;
        }
        __syncthreads();
        // phase C: fused pass — read_v partials (old mem), write update + mask,
        //          dots/norms of NEW mem against raw q_{t+1}, k_{t+1}
        {
            int tn = (t + 1 < L_) ? (t + 1) : (L_ - 1);
            const float4* Qp = (const float4*)(g_Q + (size_t)(b*L_ + tn)*D_);
            const float4* Kp = (const float4*)(g_K + (size_t)(b*L_ + tn)*D_);
            const float4* Vp = (const float4*)(g_V + (size_t)(b*L_ + t )*D_);
            float4 q0 = Qp[l], q1 = Qp[32 + l];
            float4 k0 = Kp[l], k1 = Kp[32 + l];
            float4 v0 = Vp[l], v1 = Vp[32 + l];
            float4 ra = make_float4(0.f,0.f,0.f,0.f);
            float4 rb = make_float4(0.f,0.f,0.f,0.f);
            #pragma unroll
            for (int i = 0; i < RPW; i++){
                int s = w * RPW + i;
                float rws = rw[s], p = pc[s], rcs = rc[s];
                float4 m0 = mem4[s*64 + l], m1 = mem4[s*64 + 32 + l];
                ra.x = fmaf(rws, m0.x, ra.x); ra.y = fmaf(rws, m0.y, ra.y);
                ra.z = fmaf(rws, m0.z, ra.z); ra.w = fmaf(rws, m0.w, ra.w);
                rb.x = fmaf(rws, m1.x, rb.x); rb.y = fmaf(rws, m1.y, rb.y);
                rb.z = fmaf(rws, m1.z, rb.z); rb.w = fmaf(rws, m1.w, rb.w);
                float4 n0, n1;
                n0.x = fmaf(p, m0.x, rcs * v0.x); n0.y = fmaf(p, m0.y, rcs * v0.y);
                n0.z = fmaf(p, m0.z, rcs * v0.z); n0.w = fmaf(p, m0.w, rcs * v0.w);
                n1.x = fmaf(p, m1.x, rcs * v1.x); n1.y = fmaf(p, m1.y, rcs * v1.y);
                n1.z = fmaf(p, m1.z, rcs * v1.z); n1.w = fmaf(p, m1.w, rcs * v1.w);
                mem4[s*64 + l] = n0; mem4[s*64 + 32 + l] = n1;
                float dq = dot4f(n0, q0, dot4f(n1, q1, 0.f));
                float dk = dot4f(n0, k0, dot4f(n1, k1, 0.f));
                float nn = dot4f(n0, n0, dot4f(n1, n1, 0.f));
                dq = wredsum(dq); dk = wredsum(dk); nn = wredsum(nn);
                if (l == 0){ dotq[s] = dq; dotk[s] = dk; nrm[s] = nn; }
            }
            float4* rp = (float4*)(readp + w * D_);
            rp[l] = ra; rp[32 + l] = rb;
        }
        __syncthreads();
    }
    // epilogue: read_v for t = L-1
    if (tid < D_){
        int d = tid;
        float acc = 0.f;
        #pragma unroll
        for (int j = 0; j < NW; j++) acc += readp[j*D_ + d];
        out[(size_t)(b*L_ + (L_-1))*D_ + d] = acc;
    }
}

// ---------------- launch ----------------
extern "C" void kernel_launch(void* const* d_in, const int* in_sizes, int n_in,
                              void* d_out, int out_size)
{
    const float* init_memory = (const float*)d_in[0];
    const float* hidden      = (const float*)d_in[1];
    const float* masks       = (const float*)d_in[2];
    const float* Wq = (const float*)d_in[3];
    const float* bq = (const float*)d_in[4];
    const float* Wk = (const float*)d_in[5];
    const float* bk = (const float*)d_in[6];
    const float* Wv = (const float*)d_in[7];
    const float* bv = (const float*)d_in[8];
    const float* Wg = (const float*)d_in[9];
    const float* bg = (const float*)d_in[10];
    float* out = (float*)d_out;

    float *Qp, *Kp, *Vp;
    cudaGetSymbolAddress((void**)&Qp, g_Q);
    cudaGetSymbolAddress((void**)&Kp, g_K);
    cudaGetSymbolAddress((void**)&Vp, g_V);

    dim3 ggrid(M_/64, D_/64);
    gemm_nt<<<ggrid, 256>>>(hidden, Wq, bq, Qp);
    gemm_nt<<<ggrid, 256>>>(hidden, Wk, bk, Kp);
    gemm_nt<<<ggrid, 256>>>(hidden, Wv, bv, Vp);
    gate_kernel<<<M_*32/256, 256>>>(hidden, Wg, bg);
    invnorm_kernel<<<M_*32/256, 256>>>();

    size_t smem_bytes = (size_t)(S_*D_ + 6*S_ + 16*D_ + 8) * sizeof(float);
    cudaFuncSetAttribute(recur_kernel, cudaFuncAttributeMaxDynamicSharedMemorySize,
                         (int)smem_bytes);
    recur_kernel<<<B_, 512, smem_bytes>>>(init_memory, masks, out);

    sp_kernel<<<1, 512>>>(out, out_size);
}